// round 9
// baseline (speedup 1.0000x reference)
#include <cuda_runtime.h>
#include <cuda_bf16.h>
#include <cstdint>

// SegEncodeLoss: per 32x32 block multi-hot class presence, BCE-with-logits vs preds, mean.
// Shapes fixed: B=32, H=W=1024, G=32, C=19 -> n_blocks = 32768.
//
// TMA-streamed variant: the 128MB target read goes through cp.async.bulk
// (global -> shared, mbarrier complete_tx) instead of LDG, bypassing the
// per-SM L1tex outstanding-load queue (~8KB in flight) that capped the LDG
// path at ~5.3 TB/s. One CTA per band (b,hb) = 128KB contiguous; 16 stages
// of 8KB (2 rows), depth-3 buffer ring. Thread tid consumes int4 #tid of
// each staged row -> block wb = tid/8 (mask association sync-free).

#define NUM_C   19
#define GSZ     32
#define BATCH   32
#define HDIM    1024
#define WDIM    1024
#define NBLK    (BATCH * (HDIM / GSZ) * (WDIM / GSZ))   // 32768
#define NBAND   (BATCH * (HDIM / GSZ))                  // 1024 CTAs
#define CTA_THR 256
#define ELEMS   (GSZ * NUM_C)                           // 608 loss elems per CTA

#define CHUNK_ROWS  2
#define CHUNK_BYTES (CHUNK_ROWS * WDIM * 4)             // 8192
#define DEPTH       3
#define NSTAGE      (GSZ / CHUNK_ROWS)                  // 16

__device__ double       g_acc;    // zero-init at module load; last CTA re-zeros
__device__ unsigned int g_count;  // ditto

__device__ __forceinline__ uint32_t smem_u32(const void* p) {
    return (uint32_t)__cvta_generic_to_shared(p);
}

__device__ __forceinline__ void mbar_init(uint32_t mbar, uint32_t count) {
    asm volatile("mbarrier.init.shared.b64 [%0], %1;" :: "r"(mbar), "r"(count) : "memory");
}

__device__ __forceinline__ void mbar_expect_tx(uint32_t mbar, uint32_t bytes) {
    asm volatile("mbarrier.arrive.expect_tx.shared.b64 _, [%0], %1;"
                 :: "r"(mbar), "r"(bytes) : "memory");
}

__device__ __forceinline__ void tma_bulk_g2s(uint32_t dst, const void* src,
                                             uint32_t bytes, uint32_t mbar) {
    asm volatile(
        "cp.async.bulk.shared::cta.global.mbarrier::complete_tx::bytes [%0], [%1], %2, [%3];"
        :: "r"(dst), "l"(src), "r"(bytes), "r"(mbar) : "memory");
}

__device__ __forceinline__ void mbar_wait_parity(uint32_t mbar, uint32_t parity) {
    uint32_t done;
    asm volatile(
        "{\n\t.reg .pred p;\n\t"
        "mbarrier.try_wait.parity.acquire.cta.shared::cta.b64 p, [%1], %2;\n\t"
        "selp.b32 %0, 1, 0, p;\n\t}"
        : "=r"(done) : "r"(mbar), "r"(parity) : "memory");
    if (!done) {
        asm volatile(
            "{\n\t.reg .pred P1;\n\t"
            "W_%=:\n\t"
            "mbarrier.try_wait.parity.acquire.cta.shared::cta.b64 P1, [%0], %1, 0x989680;\n\t"
            "@P1 bra.uni D_%=;\n\t"
            "bra.uni W_%=;\n\t"
            "D_%=:\n\t}"
            :: "r"(mbar), "r"(parity) : "memory");
    }
}

__global__ __launch_bounds__(CTA_THR)
void seg_loss_k(const float* __restrict__ preds, const int* __restrict__ targets,
                float* __restrict__ out) {
    __shared__ alignas(128) unsigned char s_buf[DEPTH][CHUNK_BYTES];
    __shared__ alignas(8)   uint64_t      s_mbar[DEPTH];
    __shared__ unsigned s_mask[GSZ];
    __shared__ float    s_warp[CTA_THR / 32];

    const int tid  = threadIdx.x;
    const int band = blockIdx.x;       // band = b*32 + hb; block n = band*32 + wb

    if (tid == 0) {
        #pragma unroll
        for (int d = 0; d < DEPTH; ++d) mbar_init(smem_u32(&s_mbar[d]), 1);
        asm volatile("fence.proxy.async.shared::cta;" ::: "memory");
    }
    __syncthreads();

    const char* gsrc = (const char*)(targets + (size_t)band * GSZ * WDIM);

    // Prologue: fill the ring
    if (tid == 0) {
        #pragma unroll
        for (int d = 0; d < DEPTH; ++d) {
            uint32_t mb = smem_u32(&s_mbar[d]);
            mbar_expect_tx(mb, CHUNK_BYTES);
            tma_bulk_g2s(smem_u32(&s_buf[d][0]), gsrc + (size_t)d * CHUNK_BYTES,
                         CHUNK_BYTES, mb);
        }
    }

    // ---- Phase 1: stream 16 stages of 2 rows, accumulate per-lane mask ----
    unsigned mask = 0u;
    for (int s = 0; s < NSTAGE; ++s) {
        const int slot   = s % DEPTH;
        const uint32_t parity = (uint32_t)((s / DEPTH) & 1);
        const uint32_t mb = smem_u32(&s_mbar[slot]);
        mbar_wait_parity(mb, parity);

        const int4* b = (const int4*)&s_buf[slot][0];
        int4 v0 = b[tid];                 // row 2s,   int4 #tid
        int4 v1 = b[WDIM / 4 + tid];      // row 2s+1, int4 #tid (same wb)
        mask |= (1u << v0.x) | (1u << v0.y) | (1u << v0.z) | (1u << v0.w);
        mask |= (1u << v1.x) | (1u << v1.y) | (1u << v1.z) | (1u << v1.w);

        __syncthreads();                  // everyone done with this slot
        if (tid == 0 && s + DEPTH < NSTAGE) {
            mbar_expect_tx(mb, CHUNK_BYTES);
            tma_bulk_g2s(smem_u32(&s_buf[slot][0]),
                         gsrc + (size_t)(s + DEPTH) * CHUNK_BYTES,
                         CHUNK_BYTES, mb);
        }
    }

    // OR across the 8 lanes of the group (covers all 32 columns of block wb)
    mask |= __shfl_xor_sync(0xffffffffu, mask, 1);
    mask |= __shfl_xor_sync(0xffffffffu, mask, 2);
    mask |= __shfl_xor_sync(0xffffffffu, mask, 4);
    if ((tid & 7) == 0) s_mask[tid >> 3] = mask;   // single writer per wb
    __syncthreads();

    // ---- Phase 2: BCE-with-logits over the band's 32 blocks x 19 classes ----
    const float* p = preds + (size_t)band * ELEMS;
    float val = 0.0f;
    #pragma unroll
    for (int j = tid; j < ELEMS; j += CTA_THR) {
        const float x   = __ldg(&p[j]);
        const int   blk = j / NUM_C;
        const int   c   = j - blk * NUM_C;
        const float sp  = fmaxf(x, 0.0f) + log1pf(__expf(-fabsf(x)));
        val += sp - (((s_mask[blk] >> c) & 1u) ? x : 0.0f);
    }

    // ---- CTA reduction ----
    #pragma unroll
    for (int off = 16; off; off >>= 1)
        val += __shfl_down_sync(0xffffffffu, val, off);
    if ((tid & 31) == 0) s_warp[tid >> 5] = val;
    __syncthreads();

    if (tid < 32) {
        float w = (tid < CTA_THR / 32) ? s_warp[tid] : 0.0f;
        #pragma unroll
        for (int off = 4; off; off >>= 1)
            w += __shfl_down_sync(0xffffffffu, w, off);
        if (tid == 0) {
            atomicAdd(&g_acc, (double)w);
            __threadfence();
            unsigned ticket = atomicAdd(&g_count, 1u);
            if (ticket == NBAND - 1) {
                out[0] = (float)(g_acc / (double)((long long)NBLK * NUM_C));
                g_acc   = 0.0;      // restore state for next graph replay
                g_count = 0u;
            }
        }
    }
}

extern "C" void kernel_launch(void* const* d_in, const int* in_sizes, int n_in,
                              void* d_out, int out_size) {
    const float* preds   = (const float*)d_in[0];
    const int*   targets = (const int*)d_in[1];
    // d_in[2] = grid_size (fixed at 32; shapes hardcoded)

    seg_loss_k<<<NBAND, CTA_THR>>>(preds, targets, (float*)d_out);
}

// round 13
// speedup vs baseline: 1.0479x; 1.0479x over previous
#include <cuda_runtime.h>
#include <cuda_bf16.h>
#include <cstdint>

// SegEncodeLoss: per 32x32 block multi-hot class presence, BCE-with-logits vs preds, mean.
// Shapes fixed: B=32, H=W=1024, G=32, C=19 -> n_blocks = 32768.
//
// cp.async (LDGSTS) streamed variant. The LDG path is capped by the ~64-wavefront
// per-SM outstanding-load queue (8KB in flight @ ~380cyc => ~5.6 TB/s — exactly
// what every LDG/TMA-staged variant measured). LDGSTS has no observed depth cap,
// so each thread runs a private DEPTH=4 pipeline: cp.async.cg 16B per row into
// its own SMEM slot, commit_group per iteration, wait_group(3), read own slot.
// Zero cross-thread sync in the hot loop (each thread consumes only what it loads).
// One CTA per band (b,hb) = 32 contiguous rows = 128KB; thread tid owns int4 #tid
// of every row -> block wb = tid/8 (same mask association as before).

#define NUM_C   19
#define GSZ     32
#define BATCH   32
#define HDIM    1024
#define WDIM    1024
#define NBLK    (BATCH * (HDIM / GSZ) * (WDIM / GSZ))   // 32768
#define NBAND   (BATCH * (HDIM / GSZ))                  // 1024 CTAs
#define CTA_THR 256
#define ELEMS   (GSZ * NUM_C)                           // 608 loss elems per CTA
#define DEPTH   4                                        // per-thread pipeline depth

__device__ double       g_acc;    // zero-init at module load; last CTA re-zeros
__device__ unsigned int g_count;  // ditto

__device__ __forceinline__ uint32_t smem_u32(const void* p) {
    return (uint32_t)__cvta_generic_to_shared(p);
}

__device__ __forceinline__ void cp_async16(uint32_t dst, const void* src) {
    asm volatile("cp.async.cg.shared.global [%0], [%1], 16;"
                 :: "r"(dst), "l"(src) : "memory");
}
__device__ __forceinline__ void cp_commit() {
    asm volatile("cp.async.commit_group;" ::: "memory");
}
template <int N>
__device__ __forceinline__ void cp_wait() {
    asm volatile("cp.async.wait_group %0;" :: "n"(N) : "memory");
}

__global__ __launch_bounds__(CTA_THR)
void seg_loss_k(const float* __restrict__ preds, const int* __restrict__ targets,
                float* __restrict__ out) {
    __shared__ alignas(128) int4 s_stage[DEPTH][CTA_THR];   // 16KB ring, per-thread slots
    __shared__ unsigned s_mask[GSZ];
    __shared__ float    s_warp[CTA_THR / 32];

    const int tid  = threadIdx.x;
    const int band = blockIdx.x;       // band = b*32 + hb; block n = band*32 + wb

    // Thread's gmem column: 16B chunk #tid of each 4KB row of the band.
    const char* g = (const char*)(targets + (size_t)band * GSZ * WDIM) + (size_t)tid * 16;

    // Prologue: issue rows 0..DEPTH-1, one group per row.
    #pragma unroll
    for (int d = 0; d < DEPTH; ++d) {
        cp_async16(smem_u32(&s_stage[d][tid]), g + (size_t)d * (WDIM * 4));
        cp_commit();
    }

    // ---- Phase 1: per-thread pipelined stream over 32 rows ----
    unsigned mask = 0u;
    #pragma unroll
    for (int r = 0; r < GSZ; ++r) {
        cp_wait<DEPTH - 1>();                 // group for row r complete
        int4 v = s_stage[r & (DEPTH - 1)][tid];
        mask |= (1u << v.x) | (1u << v.y) | (1u << v.z) | (1u << v.w);
        if (r + DEPTH < GSZ)
            cp_async16(smem_u32(&s_stage[r & (DEPTH - 1)][tid]),
                       g + (size_t)(r + DEPTH) * (WDIM * 4));
        cp_commit();                          // empty group on drain keeps counts aligned
    }

    // OR across the 8 lanes of the group (covers all 32 columns of block wb = tid/8)
    mask |= __shfl_xor_sync(0xffffffffu, mask, 1);
    mask |= __shfl_xor_sync(0xffffffffu, mask, 2);
    mask |= __shfl_xor_sync(0xffffffffu, mask, 4);
    if ((tid & 7) == 0) s_mask[tid >> 3] = mask;   // single writer per wb
    __syncthreads();

    // ---- Phase 2: BCE-with-logits over the band's 32 blocks x 19 classes ----
    const float* p = preds + (size_t)band * ELEMS;
    float val = 0.0f;
    #pragma unroll
    for (int j = tid; j < ELEMS; j += CTA_THR) {
        const float x   = __ldg(&p[j]);
        const int   blk = j / NUM_C;
        const int   c   = j - blk * NUM_C;
        const float sp  = fmaxf(x, 0.0f) + log1pf(__expf(-fabsf(x)));
        val += sp - (((s_mask[blk] >> c) & 1u) ? x : 0.0f);
    }

    // ---- CTA reduction ----
    #pragma unroll
    for (int off = 16; off; off >>= 1)
        val += __shfl_down_sync(0xffffffffu, val, off);
    if ((tid & 31) == 0) s_warp[tid >> 5] = val;
    __syncthreads();

    if (tid < 32) {
        float w = (tid < CTA_THR / 32) ? s_warp[tid] : 0.0f;
        #pragma unroll
        for (int off = 4; off; off >>= 1)
            w += __shfl_down_sync(0xffffffffu, w, off);
        if (tid == 0) {
            atomicAdd(&g_acc, (double)w);
            __threadfence();
            unsigned ticket = atomicAdd(&g_count, 1u);
            if (ticket == NBAND - 1) {
                out[0] = (float)(g_acc / (double)((long long)NBLK * NUM_C));
                g_acc   = 0.0;      // restore state for next graph replay
                g_count = 0u;
            }
        }
    }
}

extern "C" void kernel_launch(void* const* d_in, const int* in_sizes, int n_in,
                              void* d_out, int out_size) {
    const float* preds   = (const float*)d_in[0];
    const int*   targets = (const int*)d_in[1];
    // d_in[2] = grid_size (fixed at 32; shapes hardcoded)

    seg_loss_k<<<NBAND, CTA_THR>>>(preds, targets, (float*)d_out);
}